// round 12
// baseline (speedup 1.0000x reference)
#include <cuda_runtime.h>
#include <cuda_bf16.h>
#include <cstdint>

#define PP 1024
#define NROW 16384
#define TILE_M 128
#define TILE_N 64
#define KC 64
#define NBN (PP / TILE_N)      // 16 n-tiles
#define NSLOT NBN              // 1 ypart slot per n-tile

// smem stage layout (bytes): A 128x64 bf16 hi/lo, B 64x64 bf16 hi/lo
#define AHI 0
#define ALO 16384
#define BHI 32768
#define BLO 40960
#define STAGE_BYTES 49152
#define SMEM_TOTAL (2 * STAGE_BYTES)   // 96 KB -> 2 CTAs/SM

// prep kernel split point: X-blocks (16 floats/thread) then W-blocks
#define XBLK (NROW * PP / 16 / 256)    // 4096
#define WBLK (PP * PP / 4 / 256)       // 1024

// Scratch (static __device__ — no allocation allowed)
__device__ __align__(16) __nv_bfloat16 g_Xhi[(size_t)NROW * PP];
__device__ __align__(16) __nv_bfloat16 g_Xlo[(size_t)NROW * PP];
__device__ __align__(16) __nv_bfloat16 g_Whi[(size_t)PP * PP];   // W^T layout: [n][k]
__device__ __align__(16) __nv_bfloat16 g_Wlo[(size_t)PP * PP];
__device__ float g_ypart[(size_t)NSLOT * NROW];

// ---------------- helpers ----------------
__device__ __forceinline__ uint32_t smem_u32(const void* p) {
    uint32_t a;
    asm("{ .reg .u64 t; cvta.to.shared.u64 t, %1; cvt.u32.u64 %0, t; }" : "=r"(a) : "l"(p));
    return a;
}
// 128B rows of bf16 (64 elems). 16B chunk swizzle: chunk ^= (row & 7)
__device__ __forceinline__ uint32_t sw(int row, int ch) {
    return (uint32_t)(row * 128 + ((ch ^ (row & 7)) << 4));
}
__device__ __forceinline__ void cp16(uint32_t dst, const void* src) {
    asm volatile("cp.async.cg.shared.global [%0], [%1], 16;" :: "r"(dst), "l"(src) : "memory");
}
__device__ __forceinline__ void ldmx4(uint32_t* r, uint32_t addr) {
    asm volatile("ldmatrix.sync.aligned.m8n8.x4.shared.b16 {%0,%1,%2,%3}, [%4];"
                 : "=r"(r[0]), "=r"(r[1]), "=r"(r[2]), "=r"(r[3]) : "r"(addr));
}
__device__ __forceinline__ void mma16816(float* c, const uint32_t* a, const uint32_t* b) {
    asm volatile(
        "mma.sync.aligned.m16n8k16.row.col.f32.bf16.bf16.f32 "
        "{%0,%1,%2,%3}, {%4,%5,%6,%7}, {%8,%9}, {%0,%1,%2,%3};"
        : "+f"(c[0]), "+f"(c[1]), "+f"(c[2]), "+f"(c[3])
        : "r"(a[0]), "r"(a[1]), "r"(a[2]), "r"(a[3]), "r"(b[0]), "r"(b[1]));
}
__device__ __forceinline__ void split2(float a, float b, uint32_t& hi, uint32_t& lo) {
    __nv_bfloat16 h0 = __float2bfloat16(a);
    __nv_bfloat16 h1 = __float2bfloat16(b);
    __nv_bfloat16 l0 = __float2bfloat16(a - __bfloat162float(h0));
    __nv_bfloat16 l1 = __float2bfloat16(b - __bfloat162float(h1));
    hi = (uint32_t)__bfloat16_as_ushort(h0) | ((uint32_t)__bfloat16_as_ushort(h1) << 16);
    lo = (uint32_t)__bfloat16_as_ushort(l0) | ((uint32_t)__bfloat16_as_ushort(l1) << 16);
}

// ---------------------------------------------------------------------------
// Fused prep: blocks [0, XBLK) split X (16 floats/thread); then W^T build.
// ---------------------------------------------------------------------------
__global__ void prep_kernel(const float* __restrict__ X,
                            const float* __restrict__ theta) {
    if (blockIdx.x < XBLK) {
        size_t idx = (size_t)blockIdx.x * 256 + threadIdx.x;   // over N*P/16
#pragma unroll
        for (int h = 0; h < 2; ++h) {
            size_t q8 = idx * 2 + h;                            // 8-float unit
            float4 v0 = reinterpret_cast<const float4*>(X)[q8 * 2];
            float4 v1 = reinterpret_cast<const float4*>(X)[q8 * 2 + 1];
            float f[8] = {v0.x, v0.y, v0.z, v0.w, v1.x, v1.y, v1.z, v1.w};
            uint32_t hi[4], lo[4];
#pragma unroll
            for (int q = 0; q < 4; ++q) split2(f[2 * q], f[2 * q + 1], hi[q], lo[q]);
            reinterpret_cast<uint4*>(g_Xhi)[q8] = make_uint4(hi[0], hi[1], hi[2], hi[3]);
            reinterpret_cast<uint4*>(g_Xlo)[q8] = make_uint4(lo[0], lo[1], lo[2], lo[3]);
        }
    } else {
        int idx4 = (int)(blockIdx.x - XBLK) * 256 + threadIdx.x;  // over P*P/4
        int base = idx4 * 4;
        int n = base >> 10;
        int k0 = base & (PP - 1);     // 4 consecutive k, same n
        uint32_t hi[2], lo[2];
#pragma unroll
        for (int q = 0; q < 2; ++q) {
            float f[2];
#pragma unroll
            for (int e = 0; e < 2; ++e) {
                int k = k0 + q * 2 + e;
                f[e] = (n > k) ? theta[k * PP - ((k * (k + 1)) >> 1) + (n - k - 1)] : 0.0f;
            }
            split2(f[0], f[1], hi[q], lo[q]);
        }
        reinterpret_cast<uint2*>(g_Whi + base)[0] = make_uint2(hi[0], hi[1]);
        reinterpret_cast<uint2*>(g_Wlo + base)[0] = make_uint2(lo[0], lo[1]);
    }
}

// ---------------------------------------------------------------------------
// Main: bf16x3 mma.sync GEMM (128x64 tile, 2 CTAs/SM, 4m x 2n warp grid,
// 32x32 warp tiles) + fused (C+beta)·x rowdot epilogue.
// Triangular skip: nch_eff = bn+1. LPT heavy-first. ONE __syncthreads/chunk.
// ---------------------------------------------------------------------------
__global__ __launch_bounds__(256, 2)
void gemm_rowdot_mma(const float* __restrict__ X, const float* __restrict__ beta) {
    extern __shared__ char smem[];
    const uint32_t sbase = smem_u32(smem);
    const int tid = threadIdx.x;
    const int l = tid & 31;
    const int wid = tid >> 5;
    const int wm = wid & 3;        // 4 m-warps (32 rows each)
    const int wn = wid >> 2;       // 2 n-warps (32 cols each)
    const int m_base = wm * 32;
    const int n_base = wn * 32;

    // heavy-first decode: first 128 CTAs take bn=15, next 128 bn=14, ...
    const int bn = (NBN - 1) - (int)(blockIdx.x >> 7);
    const int bx = (int)(blockIdx.x & 127);
    const int i0 = bx * TILE_M;
    const int n0 = bn * TILE_N;
    const int nch_eff = bn + 1;    // chunks 0..bn (k0 < n0+64)

    float acc[2][4][4];            // [mi][ni][frag]
#pragma unroll
    for (int mi = 0; mi < 2; ++mi)
#pragma unroll
        for (int ni = 0; ni < 4; ++ni)
#pragma unroll
            for (int q = 0; q < 4; ++q) acc[mi][ni][q] = 0.0f;

    // --- async load of one stage ---
    auto load_stage = [&](int c) {
        const uint32_t stg = sbase + (uint32_t)(c & 1) * STAGE_BYTES;
        const int k0 = c * KC;
        // A: 128 rows x 8 ch -> 1024 slots, 4 iters (hi+lo)
#pragma unroll
        for (int it = 0; it < 4; ++it) {
            int u = tid + it * 256;
            int row = u >> 3, ch = u & 7;
            uint32_t d = sw(row, ch);
            size_t asrc = (size_t)(i0 + row) * PP + k0 + ch * 8;
            cp16(stg + AHI + d, g_Xhi + asrc);
            cp16(stg + ALO + d, g_Xlo + asrc);
        }
        // B: 64 rows x 8 ch -> 512 slots, 2 iters (hi+lo)
#pragma unroll
        for (int it = 0; it < 2; ++it) {
            int u = tid + it * 256;
            int row = u >> 3, ch = u & 7;
            uint32_t d = sw(row, ch);
            size_t bsrc = (size_t)(n0 + row) * PP + k0 + ch * 8;
            cp16(stg + BHI + d, g_Whi + bsrc);
            cp16(stg + BLO + d, g_Wlo + bsrc);
        }
        asm volatile("cp.async.commit_group;" ::: "memory");
    };

    load_stage(0);

    for (int c = 0; c < nch_eff; ++c) {
        // my chunk-c cp.asyncs done; barrier publishes all threads' data AND
        // proves all warps finished chunk c-1 -> its stage is reusable.
        asm volatile("cp.async.wait_group 0;" ::: "memory");
        __syncthreads();
        if (c + 1 < nch_eff) load_stage(c + 1);

        const uint32_t stg = sbase + (uint32_t)(c & 1) * STAGE_BYTES;
#pragma unroll
        for (int ks = 0; ks < 4; ++ks) {
            uint32_t ahi[2][4], alo[2][4], bhi[4][2], blo[4][2];
            // A fragments: lanes 0-15 rows r (k-lo half), lanes 16-31 (k-hi)
            {
                int r = l & 15, kh = l >> 4;
                int ch = ks * 2 + kh;
#pragma unroll
                for (int mi = 0; mi < 2; ++mi) {
                    uint32_t ad = sw(m_base + mi * 16 + r, ch);
                    ldmx4(ahi[mi], stg + AHI + ad);
                    ldmx4(alo[mi], stg + ALO + ad);
                }
            }
            // B fragments: 2 x ldmatrix.x4 (x hi/lo) cover 32 n-rows x k16
            {
                int nr_off = ((l >> 4) << 3) + (l & 7);
                int ch = ks * 2 + ((l >> 3) & 1);
#pragma unroll
                for (int np = 0; np < 2; ++np) {
                    uint32_t bd = sw(n_base + np * 16 + nr_off, ch);
                    uint32_t r4[4];
                    ldmx4(r4, stg + BHI + bd);
                    bhi[np * 2][0] = r4[0]; bhi[np * 2][1] = r4[1];
                    bhi[np * 2 + 1][0] = r4[2]; bhi[np * 2 + 1][1] = r4[3];
                    ldmx4(r4, stg + BLO + bd);
                    blo[np * 2][0] = r4[0]; blo[np * 2][1] = r4[1];
                    blo[np * 2 + 1][0] = r4[2]; blo[np * 2 + 1][1] = r4[3];
                }
            }
#pragma unroll
            for (int mi = 0; mi < 2; ++mi)
#pragma unroll
                for (int ni = 0; ni < 4; ++ni) {
                    mma16816(acc[mi][ni], ahi[mi], bhi[ni]);
                    mma16816(acc[mi][ni], ahi[mi], blo[ni]);
                    mma16816(acc[mi][ni], alo[mi], bhi[ni]);
                }
        }
    }
    __syncthreads();   // all warps done with last chunk before smem reuse

    // --- fused epilogue: part_r = sum_c (C[r][c] + beta[c]) * X[r][c] ---
    float* sarr = (float*)smem;    // 2*128 floats
#pragma unroll
    for (int mi = 0; mi < 2; ++mi) {
        int tr0 = m_base + mi * 16 + (l >> 2);
        int tr1 = tr0 + 8;
        int r0 = i0 + tr0;
        int r1 = i0 + tr1;
        float p0 = 0.0f, p1 = 0.0f;
#pragma unroll
        for (int ni = 0; ni < 4; ++ni) {
            int cc = n0 + n_base + ni * 8 + (l & 3) * 2;
            float2 bv  = *(const float2*)&beta[cc];
            float2 x0  = *(const float2*)&X[(size_t)r0 * PP + cc];
            float2 x1  = *(const float2*)&X[(size_t)r1 * PP + cc];
            p0 = fmaf(acc[mi][ni][0] + bv.x, x0.x, p0);
            p0 = fmaf(acc[mi][ni][1] + bv.y, x0.y, p0);
            p1 = fmaf(acc[mi][ni][2] + bv.x, x1.x, p1);
            p1 = fmaf(acc[mi][ni][3] + bv.y, x1.y, p1);
        }
        p0 += __shfl_xor_sync(0xffffffffu, p0, 1);
        p0 += __shfl_xor_sync(0xffffffffu, p0, 2);
        p1 += __shfl_xor_sync(0xffffffffu, p1, 1);
        p1 += __shfl_xor_sync(0xffffffffu, p1, 2);
        if ((l & 3) == 0) {
            sarr[wn * 128 + tr0] = p0;
            sarr[wn * 128 + tr1] = p1;
        }
    }
    __syncthreads();
    if (tid < 128) {
        float s = sarr[tid] + sarr[128 + tid];
        g_ypart[(size_t)bn * NROW + i0 + tid] = s;
    }
}

// ---------------------------------------------------------------------------
// Final: y[i] = beta0 + sum of 16 partials
// ---------------------------------------------------------------------------
__global__ void reduce_kernel(const float* __restrict__ beta0, float* __restrict__ y) {
    int i = blockIdx.x * blockDim.x + threadIdx.x;
    if (i >= NROW) return;
    float s = beta0[0];
#pragma unroll
    for (int g = 0; g < NSLOT; ++g) s += g_ypart[(size_t)g * NROW + i];
    y[i] = s;
}

extern "C" void kernel_launch(void* const* d_in, const int* in_sizes, int n_in,
                              void* d_out, int out_size) {
    const float* X     = (const float*)d_in[0];
    const float* beta0 = (const float*)d_in[1];
    const float* beta  = (const float*)d_in[2];
    const float* theta = (const float*)d_in[3];
    float* y = (float*)d_out;

    cudaFuncSetAttribute(gemm_rowdot_mma, cudaFuncAttributeMaxDynamicSharedMemorySize, SMEM_TOTAL);

    prep_kernel<<<XBLK + WBLK, 256>>>(X, theta);

    gemm_rowdot_mma<<<NBN * 128, 256, SMEM_TOTAL>>>(X, beta);

    reduce_kernel<<<(NROW + 255) / 256, 256>>>(beta0, y);
}

// round 13
// speedup vs baseline: 1.0409x; 1.0409x over previous
#include <cuda_runtime.h>
#include <cuda_bf16.h>
#include <cstdint>

#define PP 1024
#define NROW 16384
#define TILE_M 128
#define TILE_N 64
#define KC 64
#define NBN (PP / TILE_N)      // 16 n-tiles
#define NSLOT NBN              // 1 ypart slot per n-tile

// smem stage layout (bytes): A 128x64 bf16 hi/lo, B 64x64 bf16 hi/lo
#define AHI 0
#define ALO 16384
#define BHI 32768
#define BLO 40960
#define STAGE_BYTES 49152
#define SMEM_TOTAL (2 * STAGE_BYTES)   // 96 KB -> 2 CTAs/SM

// prep kernel split point: X-blocks (8 floats/thread) then W-blocks
#define XBLK (NROW * PP / 8 / 256)     // 8192
#define WBLK (PP * PP / 4 / 256)       // 1024

// Scratch (static __device__ — no allocation allowed)
__device__ __align__(16) __nv_bfloat16 g_Xhi[(size_t)NROW * PP];
__device__ __align__(16) __nv_bfloat16 g_Xlo[(size_t)NROW * PP];
__device__ __align__(16) __nv_bfloat16 g_Whi[(size_t)PP * PP];   // W^T layout: [n][k]
__device__ __align__(16) __nv_bfloat16 g_Wlo[(size_t)PP * PP];
__device__ float g_ypart[(size_t)NSLOT * NROW];

// ---------------- helpers ----------------
__device__ __forceinline__ uint32_t smem_u32(const void* p) {
    uint32_t a;
    asm("{ .reg .u64 t; cvta.to.shared.u64 t, %1; cvt.u32.u64 %0, t; }" : "=r"(a) : "l"(p));
    return a;
}
// 128B rows of bf16 (64 elems). 16B chunk swizzle: chunk ^= (row & 7)
__device__ __forceinline__ uint32_t sw(int row, int ch) {
    return (uint32_t)(row * 128 + ((ch ^ (row & 7)) << 4));
}
__device__ __forceinline__ void cp16(uint32_t dst, const void* src) {
    asm volatile("cp.async.cg.shared.global [%0], [%1], 16;" :: "r"(dst), "l"(src) : "memory");
}
__device__ __forceinline__ void ldmx4(uint32_t* r, uint32_t addr) {
    asm volatile("ldmatrix.sync.aligned.m8n8.x4.shared.b16 {%0,%1,%2,%3}, [%4];"
                 : "=r"(r[0]), "=r"(r[1]), "=r"(r[2]), "=r"(r[3]) : "r"(addr));
}
__device__ __forceinline__ void mma16816(float* c, const uint32_t* a, const uint32_t* b) {
    asm volatile(
        "mma.sync.aligned.m16n8k16.row.col.f32.bf16.bf16.f32 "
        "{%0,%1,%2,%3}, {%4,%5,%6,%7}, {%8,%9}, {%0,%1,%2,%3};"
        : "+f"(c[0]), "+f"(c[1]), "+f"(c[2]), "+f"(c[3])
        : "r"(a[0]), "r"(a[1]), "r"(a[2]), "r"(a[3]), "r"(b[0]), "r"(b[1]));
}
__device__ __forceinline__ void split2(float a, float b, uint32_t& hi, uint32_t& lo) {
    __nv_bfloat16 h0 = __float2bfloat16(a);
    __nv_bfloat16 h1 = __float2bfloat16(b);
    __nv_bfloat16 l0 = __float2bfloat16(a - __bfloat162float(h0));
    __nv_bfloat16 l1 = __float2bfloat16(b - __bfloat162float(h1));
    hi = (uint32_t)__bfloat16_as_ushort(h0) | ((uint32_t)__bfloat16_as_ushort(h1) << 16);
    lo = (uint32_t)__bfloat16_as_ushort(l0) | ((uint32_t)__bfloat16_as_ushort(l1) << 16);
}

// ---------------------------------------------------------------------------
// Fused prep (R10 version — measured 22 us): blocks [0, XBLK) split X
// (8 floats/thread, 16B stores); blocks [XBLK, XBLK+WBLK) build W^T.
// ---------------------------------------------------------------------------
__global__ void prep_kernel(const float* __restrict__ X,
                            const float* __restrict__ theta) {
    if (blockIdx.x < XBLK) {
        size_t idx = (size_t)blockIdx.x * 256 + threadIdx.x;   // over N*P/8
        float4 v0 = reinterpret_cast<const float4*>(X)[idx * 2];
        float4 v1 = reinterpret_cast<const float4*>(X)[idx * 2 + 1];
        float f[8] = {v0.x, v0.y, v0.z, v0.w, v1.x, v1.y, v1.z, v1.w};
        uint32_t hi[4], lo[4];
#pragma unroll
        for (int q = 0; q < 4; ++q) split2(f[2 * q], f[2 * q + 1], hi[q], lo[q]);
        reinterpret_cast<uint4*>(g_Xhi)[idx] = make_uint4(hi[0], hi[1], hi[2], hi[3]);
        reinterpret_cast<uint4*>(g_Xlo)[idx] = make_uint4(lo[0], lo[1], lo[2], lo[3]);
    } else {
        int idx4 = (int)(blockIdx.x - XBLK) * 256 + threadIdx.x;  // over P*P/4
        int base = idx4 * 4;
        int n = base >> 10;
        int k0 = base & (PP - 1);     // 4 consecutive k, same n
        uint32_t hi[2], lo[2];
#pragma unroll
        for (int q = 0; q < 2; ++q) {
            float f[2];
#pragma unroll
            for (int e = 0; e < 2; ++e) {
                int k = k0 + q * 2 + e;
                f[e] = (n > k) ? theta[k * PP - ((k * (k + 1)) >> 1) + (n - k - 1)] : 0.0f;
            }
            split2(f[0], f[1], hi[q], lo[q]);
        }
        reinterpret_cast<uint2*>(g_Whi + base)[0] = make_uint2(hi[0], hi[1]);
        reinterpret_cast<uint2*>(g_Wlo + base)[0] = make_uint2(lo[0], lo[1]);
    }
}

// ---------------------------------------------------------------------------
// Main: bf16x3 mma.sync GEMM (128x64 tile, 2 CTAs/SM, 4m x 2n warp grid,
// 32x32 warp tiles) + fused (C+beta)·x rowdot epilogue.
// Triangular skip: nch_eff = bn+1. LPT heavy-first. ONE __syncthreads/chunk.
// ---------------------------------------------------------------------------
__global__ __launch_bounds__(256, 2)
void gemm_rowdot_mma(const float* __restrict__ X, const float* __restrict__ beta) {
    extern __shared__ char smem[];
    const uint32_t sbase = smem_u32(smem);
    const int tid = threadIdx.x;
    const int l = tid & 31;
    const int wid = tid >> 5;
    const int wm = wid & 3;        // 4 m-warps (32 rows each)
    const int wn = wid >> 2;       // 2 n-warps (32 cols each)
    const int m_base = wm * 32;
    const int n_base = wn * 32;

    // heavy-first decode: first 128 CTAs take bn=15, next 128 bn=14, ...
    const int bn = (NBN - 1) - (int)(blockIdx.x >> 7);
    const int bx = (int)(blockIdx.x & 127);
    const int i0 = bx * TILE_M;
    const int n0 = bn * TILE_N;
    const int nch_eff = bn + 1;    // chunks 0..bn (k0 < n0+64)

    float acc[2][4][4];            // [mi][ni][frag]
#pragma unroll
    for (int mi = 0; mi < 2; ++mi)
#pragma unroll
        for (int ni = 0; ni < 4; ++ni)
#pragma unroll
            for (int q = 0; q < 4; ++q) acc[mi][ni][q] = 0.0f;

    // --- async load of one stage ---
    auto load_stage = [&](int c) {
        const uint32_t stg = sbase + (uint32_t)(c & 1) * STAGE_BYTES;
        const int k0 = c * KC;
        // A: 128 rows x 8 ch -> 1024 slots, 4 iters (hi+lo)
#pragma unroll
        for (int it = 0; it < 4; ++it) {
            int u = tid + it * 256;
            int row = u >> 3, ch = u & 7;
            uint32_t d = sw(row, ch);
            size_t asrc = (size_t)(i0 + row) * PP + k0 + ch * 8;
            cp16(stg + AHI + d, g_Xhi + asrc);
            cp16(stg + ALO + d, g_Xlo + asrc);
        }
        // B: 64 rows x 8 ch -> 512 slots, 2 iters (hi+lo)
#pragma unroll
        for (int it = 0; it < 2; ++it) {
            int u = tid + it * 256;
            int row = u >> 3, ch = u & 7;
            uint32_t d = sw(row, ch);
            size_t bsrc = (size_t)(n0 + row) * PP + k0 + ch * 8;
            cp16(stg + BHI + d, g_Whi + bsrc);
            cp16(stg + BLO + d, g_Wlo + bsrc);
        }
        asm volatile("cp.async.commit_group;" ::: "memory");
    };

    load_stage(0);

    for (int c = 0; c < nch_eff; ++c) {
        // my chunk-c cp.asyncs done; barrier publishes all threads' data AND
        // proves all warps finished chunk c-1 -> its stage is reusable.
        asm volatile("cp.async.wait_group 0;" ::: "memory");
        __syncthreads();
        if (c + 1 < nch_eff) load_stage(c + 1);

        const uint32_t stg = sbase + (uint32_t)(c & 1) * STAGE_BYTES;
#pragma unroll
        for (int ks = 0; ks < 4; ++ks) {
            uint32_t ahi[2][4], alo[2][4], bhi[4][2], blo[4][2];
            // A fragments: lanes 0-15 rows r (k-lo half), lanes 16-31 (k-hi)
            {
                int r = l & 15, kh = l >> 4;
                int ch = ks * 2 + kh;
#pragma unroll
                for (int mi = 0; mi < 2; ++mi) {
                    uint32_t ad = sw(m_base + mi * 16 + r, ch);
                    ldmx4(ahi[mi], stg + AHI + ad);
                    ldmx4(alo[mi], stg + ALO + ad);
                }
            }
            // B fragments: 2 x ldmatrix.x4 (x hi/lo) cover 32 n-rows x k16
            {
                int nr_off = ((l >> 4) << 3) + (l & 7);
                int ch = ks * 2 + ((l >> 3) & 1);
#pragma unroll
                for (int np = 0; np < 2; ++np) {
                    uint32_t bd = sw(n_base + np * 16 + nr_off, ch);
                    uint32_t r4[4];
                    ldmx4(r4, stg + BHI + bd);
                    bhi[np * 2][0] = r4[0]; bhi[np * 2][1] = r4[1];
                    bhi[np * 2 + 1][0] = r4[2]; bhi[np * 2 + 1][1] = r4[3];
                    ldmx4(r4, stg + BLO + bd);
                    blo[np * 2][0] = r4[0]; blo[np * 2][1] = r4[1];
                    blo[np * 2 + 1][0] = r4[2]; blo[np * 2 + 1][1] = r4[3];
                }
            }
#pragma unroll
            for (int mi = 0; mi < 2; ++mi)
#pragma unroll
                for (int ni = 0; ni < 4; ++ni) {
                    mma16816(acc[mi][ni], ahi[mi], bhi[ni]);
                    mma16816(acc[mi][ni], ahi[mi], blo[ni]);
                    mma16816(acc[mi][ni], alo[mi], bhi[ni]);
                }
        }
    }
    __syncthreads();   // all warps done with last chunk before smem reuse

    // --- fused epilogue: part_r = sum_c (C[r][c] + beta[c]) * X[r][c] ---
    float* sarr = (float*)smem;    // 2*128 floats
#pragma unroll
    for (int mi = 0; mi < 2; ++mi) {
        int tr0 = m_base + mi * 16 + (l >> 2);
        int tr1 = tr0 + 8;
        int r0 = i0 + tr0;
        int r1 = i0 + tr1;
        float p0 = 0.0f, p1 = 0.0f;
#pragma unroll
        for (int ni = 0; ni < 4; ++ni) {
            int cc = n0 + n_base + ni * 8 + (l & 3) * 2;
            float2 bv  = *(const float2*)&beta[cc];
            float2 x0  = *(const float2*)&X[(size_t)r0 * PP + cc];
            float2 x1  = *(const float2*)&X[(size_t)r1 * PP + cc];
            p0 = fmaf(acc[mi][ni][0] + bv.x, x0.x, p0);
            p0 = fmaf(acc[mi][ni][1] + bv.y, x0.y, p0);
            p1 = fmaf(acc[mi][ni][2] + bv.x, x1.x, p1);
            p1 = fmaf(acc[mi][ni][3] + bv.y, x1.y, p1);
        }
        p0 += __shfl_xor_sync(0xffffffffu, p0, 1);
        p0 += __shfl_xor_sync(0xffffffffu, p0, 2);
        p1 += __shfl_xor_sync(0xffffffffu, p1, 1);
        p1 += __shfl_xor_sync(0xffffffffu, p1, 2);
        if ((l & 3) == 0) {
            sarr[wn * 128 + tr0] = p0;
            sarr[wn * 128 + tr1] = p1;
        }
    }
    __syncthreads();
    if (tid < 128) {
        float s = sarr[tid] + sarr[128 + tid];
        g_ypart[(size_t)bn * NROW + i0 + tid] = s;
    }
}

// ---------------------------------------------------------------------------
// Final: y[i] = beta0 + sum of 16 partials
// ---------------------------------------------------------------------------
__global__ void reduce_kernel(const float* __restrict__ beta0, float* __restrict__ y) {
    int i = blockIdx.x * blockDim.x + threadIdx.x;
    if (i >= NROW) return;
    float s = beta0[0];
#pragma unroll
    for (int g = 0; g < NSLOT; ++g) s += g_ypart[(size_t)g * NROW + i];
    y[i] = s;
}

extern "C" void kernel_launch(void* const* d_in, const int* in_sizes, int n_in,
                              void* d_out, int out_size) {
    const float* X     = (const float*)d_in[0];
    const float* beta0 = (const float*)d_in[1];
    const float* beta  = (const float*)d_in[2];
    const float* theta = (const float*)d_in[3];
    float* y = (float*)d_out;

    cudaFuncSetAttribute(gemm_rowdot_mma, cudaFuncAttributeMaxDynamicSharedMemorySize, SMEM_TOTAL);

    prep_kernel<<<XBLK + WBLK, 256>>>(X, theta);

    gemm_rowdot_mma<<<NBN * 128, 256, SMEM_TOTAL>>>(X, beta);

    reduce_kernel<<<(NROW + 255) / 256, 256>>>(beta0, y);
}

// round 14
// speedup vs baseline: 1.0515x; 1.0102x over previous
#include <cuda_runtime.h>
#include <cuda_bf16.h>
#include <cstdint>

#define PP 1024
#define NROW 16384
#define TILE_M 128
#define TILE_N 64
#define KC 64
#define NBN (PP / TILE_N)      // 16 n-tiles
#define NSLOT NBN              // 1 ypart slot per n-tile

// smem stage layout (bytes): A 128x64 bf16 hi/lo, B 64x64 bf16 hi/lo
#define AHI 0
#define ALO 16384
#define BHI 32768
#define BLO 40960
#define STAGE_BYTES 49152
#define SMEM_TOTAL (2 * STAGE_BYTES)   // 96 KB -> 2 CTAs/SM

// prep kernel split point: X-blocks (8 floats/thread) then W-blocks
#define XBLK (NROW * PP / 8 / 256)     // 8192
#define WBLK (PP * PP / 4 / 256)       // 1024

// Scratch (static __device__ — no allocation allowed)
__device__ __align__(16) __nv_bfloat16 g_Xhi[(size_t)NROW * PP];
__device__ __align__(16) __nv_bfloat16 g_Xlo[(size_t)NROW * PP];
__device__ __align__(16) __nv_bfloat16 g_Whi[(size_t)PP * PP];   // W^T layout: [n][k]
__device__ __align__(16) __nv_bfloat16 g_Wlo[(size_t)PP * PP];
__device__ float g_ypart[(size_t)NSLOT * NROW];

// ---------------- helpers ----------------
__device__ __forceinline__ uint32_t smem_u32(const void* p) {
    uint32_t a;
    asm("{ .reg .u64 t; cvta.to.shared.u64 t, %1; cvt.u32.u64 %0, t; }" : "=r"(a) : "l"(p));
    return a;
}
// 128B rows of bf16 (64 elems). 16B chunk swizzle: chunk ^= (row & 7)
__device__ __forceinline__ uint32_t sw(int row, int ch) {
    return (uint32_t)(row * 128 + ((ch ^ (row & 7)) << 4));
}
__device__ __forceinline__ void cp16(uint32_t dst, const void* src) {
    asm volatile("cp.async.cg.shared.global [%0], [%1], 16;" :: "r"(dst), "l"(src) : "memory");
}
__device__ __forceinline__ void ldmx4(uint32_t* r, uint32_t addr) {
    asm volatile("ldmatrix.sync.aligned.m8n8.x4.shared.b16 {%0,%1,%2,%3}, [%4];"
                 : "=r"(r[0]), "=r"(r[1]), "=r"(r[2]), "=r"(r[3]) : "r"(addr));
}
__device__ __forceinline__ void mma16816(float* c, const uint32_t* a, const uint32_t* b) {
    asm volatile(
        "mma.sync.aligned.m16n8k16.row.col.f32.bf16.bf16.f32 "
        "{%0,%1,%2,%3}, {%4,%5,%6,%7}, {%8,%9}, {%0,%1,%2,%3};"
        : "+f"(c[0]), "+f"(c[1]), "+f"(c[2]), "+f"(c[3])
        : "r"(a[0]), "r"(a[1]), "r"(a[2]), "r"(a[3]), "r"(b[0]), "r"(b[1]));
}
__device__ __forceinline__ void split2(float a, float b, uint32_t& hi, uint32_t& lo) {
    __nv_bfloat16 h0 = __float2bfloat16(a);
    __nv_bfloat16 h1 = __float2bfloat16(b);
    __nv_bfloat16 l0 = __float2bfloat16(a - __bfloat162float(h0));
    __nv_bfloat16 l1 = __float2bfloat16(b - __bfloat162float(h1));
    hi = (uint32_t)__bfloat16_as_ushort(h0) | ((uint32_t)__bfloat16_as_ushort(h1) << 16);
    lo = (uint32_t)__bfloat16_as_ushort(l0) | ((uint32_t)__bfloat16_as_ushort(l1) << 16);
}

// fragment double-buffer
struct Frags {
    uint32_t ahi[2][4], alo[2][4];
    uint32_t bhi[4][2], blo[4][2];
};

// ---------------------------------------------------------------------------
// Fused prep (R10/R12 version — measured 22 us)
// ---------------------------------------------------------------------------
__global__ void prep_kernel(const float* __restrict__ X,
                            const float* __restrict__ theta) {
    if (blockIdx.x < XBLK) {
        size_t idx = (size_t)blockIdx.x * 256 + threadIdx.x;   // over N*P/8
        float4 v0 = reinterpret_cast<const float4*>(X)[idx * 2];
        float4 v1 = reinterpret_cast<const float4*>(X)[idx * 2 + 1];
        float f[8] = {v0.x, v0.y, v0.z, v0.w, v1.x, v1.y, v1.z, v1.w};
        uint32_t hi[4], lo[4];
#pragma unroll
        for (int q = 0; q < 4; ++q) split2(f[2 * q], f[2 * q + 1], hi[q], lo[q]);
        reinterpret_cast<uint4*>(g_Xhi)[idx] = make_uint4(hi[0], hi[1], hi[2], hi[3]);
        reinterpret_cast<uint4*>(g_Xlo)[idx] = make_uint4(lo[0], lo[1], lo[2], lo[3]);
    } else {
        int idx4 = (int)(blockIdx.x - XBLK) * 256 + threadIdx.x;  // over P*P/4
        int base = idx4 * 4;
        int n = base >> 10;
        int k0 = base & (PP - 1);     // 4 consecutive k, same n
        uint32_t hi[2], lo[2];
#pragma unroll
        for (int q = 0; q < 2; ++q) {
            float f[2];
#pragma unroll
            for (int e = 0; e < 2; ++e) {
                int k = k0 + q * 2 + e;
                f[e] = (n > k) ? theta[k * PP - ((k * (k + 1)) >> 1) + (n - k - 1)] : 0.0f;
            }
            split2(f[0], f[1], hi[q], lo[q]);
        }
        reinterpret_cast<uint2*>(g_Whi + base)[0] = make_uint2(hi[0], hi[1]);
        reinterpret_cast<uint2*>(g_Wlo + base)[0] = make_uint2(lo[0], lo[1]);
    }
}

// ---------------------------------------------------------------------------
// Main: bf16x3 mma.sync GEMM (128x64 tile, 2 CTAs/SM, 4m x 2n warp grid,
// 32x32 warp tiles, software-pipelined fragment loads) + fused rowdot epilogue.
// Triangular skip: nch_eff = bn+1. LPT heavy-first. ONE __syncthreads/chunk.
// ---------------------------------------------------------------------------
__global__ __launch_bounds__(256, 2)
void gemm_rowdot_mma(const float* __restrict__ X, const float* __restrict__ beta) {
    extern __shared__ char smem[];
    const uint32_t sbase = smem_u32(smem);
    const int tid = threadIdx.x;
    const int l = tid & 31;
    const int wid = tid >> 5;
    const int wm = wid & 3;        // 4 m-warps (32 rows each)
    const int wn = wid >> 2;       // 2 n-warps (32 cols each)
    const int m_base = wm * 32;
    const int n_base = wn * 32;

    // heavy-first decode: first 128 CTAs take bn=15, next 128 bn=14, ...
    const int bn = (NBN - 1) - (int)(blockIdx.x >> 7);
    const int bx = (int)(blockIdx.x & 127);
    const int i0 = bx * TILE_M;
    const int n0 = bn * TILE_N;
    const int nch_eff = bn + 1;    // chunks 0..bn (k0 < n0+64)

    // precomputed per-thread fragment addressing
    const int a_r  = l & 15;
    const int a_kh = l >> 4;
    const int b_nr = ((l >> 4) << 3) + (l & 7);
    const int b_kh = (l >> 3) & 1;

    float acc[2][4][4];            // [mi][ni][frag]
#pragma unroll
    for (int mi = 0; mi < 2; ++mi)
#pragma unroll
        for (int ni = 0; ni < 4; ++ni)
#pragma unroll
            for (int q = 0; q < 4; ++q) acc[mi][ni][q] = 0.0f;

    // --- async load of one stage ---
    auto load_stage = [&](int c) {
        const uint32_t stg = sbase + (uint32_t)(c & 1) * STAGE_BYTES;
        const int k0 = c * KC;
#pragma unroll
        for (int it = 0; it < 4; ++it) {
            int u = tid + it * 256;
            int row = u >> 3, ch = u & 7;
            uint32_t d = sw(row, ch);
            size_t asrc = (size_t)(i0 + row) * PP + k0 + ch * 8;
            cp16(stg + AHI + d, g_Xhi + asrc);
            cp16(stg + ALO + d, g_Xlo + asrc);
        }
#pragma unroll
        for (int it = 0; it < 2; ++it) {
            int u = tid + it * 256;
            int row = u >> 3, ch = u & 7;
            uint32_t d = sw(row, ch);
            size_t bsrc = (size_t)(n0 + row) * PP + k0 + ch * 8;
            cp16(stg + BHI + d, g_Whi + bsrc);
            cp16(stg + BLO + d, g_Wlo + bsrc);
        }
        asm volatile("cp.async.commit_group;" ::: "memory");
    };

    // --- load fragments for one k16 step into a buffer ---
    auto load_frags = [&](uint32_t stg, int ks, Frags& F) {
        int cha = ks * 2 + a_kh;
#pragma unroll
        for (int mi = 0; mi < 2; ++mi) {
            uint32_t ad = sw(m_base + mi * 16 + a_r, cha);
            ldmx4(F.ahi[mi], stg + AHI + ad);
            ldmx4(F.alo[mi], stg + ALO + ad);
        }
        int chb = ks * 2 + b_kh;
#pragma unroll
        for (int np = 0; np < 2; ++np) {
            uint32_t bd = sw(n_base + np * 16 + b_nr, chb);
            uint32_t r4[4];
            ldmx4(r4, stg + BHI + bd);
            F.bhi[np * 2][0] = r4[0]; F.bhi[np * 2][1] = r4[1];
            F.bhi[np * 2 + 1][0] = r4[2]; F.bhi[np * 2 + 1][1] = r4[3];
            ldmx4(r4, stg + BLO + bd);
            F.blo[np * 2][0] = r4[0]; F.blo[np * 2][1] = r4[1];
            F.blo[np * 2 + 1][0] = r4[2]; F.blo[np * 2 + 1][1] = r4[3];
        }
    };

    Frags fb[2];
    load_stage(0);

    for (int c = 0; c < nch_eff; ++c) {
        asm volatile("cp.async.wait_group 0;" ::: "memory");
        __syncthreads();
        if (c + 1 < nch_eff) load_stage(c + 1);

        const uint32_t stg = sbase + (uint32_t)(c & 1) * STAGE_BYTES;
        load_frags(stg, 0, fb[0]);
#pragma unroll
        for (int ks = 0; ks < 4; ++ks) {
            // prefetch next k-step's fragments before this step's MMAs
            if (ks < 3) load_frags(stg, ks + 1, fb[(ks + 1) & 1]);
            Frags& F = fb[ks & 1];
#pragma unroll
            for (int mi = 0; mi < 2; ++mi)
#pragma unroll
                for (int ni = 0; ni < 4; ++ni) {
                    mma16816(acc[mi][ni], F.ahi[mi], F.bhi[ni]);
                    mma16816(acc[mi][ni], F.ahi[mi], F.blo[ni]);
                    mma16816(acc[mi][ni], F.alo[mi], F.bhi[ni]);
                }
        }
    }
    __syncthreads();   // all warps done with last chunk before smem reuse

    // --- fused epilogue: part_r = sum_c (C[r][c] + beta[c]) * X[r][c] ---
    float* sarr = (float*)smem;    // 2*128 floats
#pragma unroll
    for (int mi = 0; mi < 2; ++mi) {
        int tr0 = m_base + mi * 16 + (l >> 2);
        int tr1 = tr0 + 8;
        int r0 = i0 + tr0;
        int r1 = i0 + tr1;
        float p0 = 0.0f, p1 = 0.0f;
#pragma unroll
        for (int ni = 0; ni < 4; ++ni) {
            int cc = n0 + n_base + ni * 8 + (l & 3) * 2;
            float2 bv  = *(const float2*)&beta[cc];
            float2 x0  = *(const float2*)&X[(size_t)r0 * PP + cc];
            float2 x1  = *(const float2*)&X[(size_t)r1 * PP + cc];
            p0 = fmaf(acc[mi][ni][0] + bv.x, x0.x, p0);
            p0 = fmaf(acc[mi][ni][1] + bv.y, x0.y, p0);
            p1 = fmaf(acc[mi][ni][2] + bv.x, x1.x, p1);
            p1 = fmaf(acc[mi][ni][3] + bv.y, x1.y, p1);
        }
        p0 += __shfl_xor_sync(0xffffffffu, p0, 1);
        p0 += __shfl_xor_sync(0xffffffffu, p0, 2);
        p1 += __shfl_xor_sync(0xffffffffu, p1, 1);
        p1 += __shfl_xor_sync(0xffffffffu, p1, 2);
        if ((l & 3) == 0) {
            sarr[wn * 128 + tr0] = p0;
            sarr[wn * 128 + tr1] = p1;
        }
    }
    __syncthreads();
    if (tid < 128) {
        float s = sarr[tid] + sarr[128 + tid];
        g_ypart[(size_t)bn * NROW + i0 + tid] = s;
    }
}

// ---------------------------------------------------------------------------
// Final: y[i] = beta0 + sum of 16 partials
// ---------------------------------------------------------------------------
__global__ void reduce_kernel(const float* __restrict__ beta0, float* __restrict__ y) {
    int i = blockIdx.x * blockDim.x + threadIdx.x;
    if (i >= NROW) return;
    float s = beta0[0];
#pragma unroll
    for (int g = 0; g < NSLOT; ++g) s += g_ypart[(size_t)g * NROW + i];
    y[i] = s;
}

extern "C" void kernel_launch(void* const* d_in, const int* in_sizes, int n_in,
                              void* d_out, int out_size) {
    const float* X     = (const float*)d_in[0];
    const float* beta0 = (const float*)d_in[1];
    const float* beta  = (const float*)d_in[2];
    const float* theta = (const float*)d_in[3];
    float* y = (float*)d_out;

    cudaFuncSetAttribute(gemm_rowdot_mma, cudaFuncAttributeMaxDynamicSharedMemorySize, SMEM_TOTAL);

    prep_kernel<<<XBLK + WBLK, 256>>>(X, theta);

    gemm_rowdot_mma<<<NBN * 128, 256, SMEM_TOTAL>>>(X, beta);

    reduce_kernel<<<(NROW + 255) / 256, 256>>>(beta0, y);
}